// round 15
// baseline (speedup 1.0000x reference)
#include <cuda_runtime.h>
#include <cuda_fp16.h>
#include <cstdint>
#include <cstddef>

// ---------------- problem dims ----------------
#define B_   256
#define IV   1000
#define D_   800
#define H1_  256
#define H2_  16
#define PH_  256

// ---------------- section tiling ----------------
#define IT_M  128                 // intervals per CTA (N dim of GEMM)
#define NIT   8                   // 8*128 = 1024 >= 1000
#define KS    80                  // K per stage
#define NST   (D_ / KS)           // 10 stages
// double-buffer ring (2 slots) for A + B-f32; Bh (packed fp16 B) single buffer

// SMEM layout (bytes)
// A slot:  256 rows x 176 B (160 B fp16 data + 16 B pad; ldmatrix bank-clean)
// Bf slot: 80 rows x 560 B (140 floats; cp.async landing pad)
// Bh:      40 rows x 544 B (136 u32; word = f16x2(B[2k2][i], B[2k2+1][i]);
//          stride 136 == 8 mod 32 -> 4row x 8col frag reads hit 32 banks)
#define ASLOT   45056
#define BSLOT   44800
#define A_SL(s)   ((s) * ASLOT)             // 0 / 45056 ; end 90112
#define BF_SL(s)  (90112 + (s) * BSLOT)     // 90112 / 134912 ; end 179712
#define BH_OFF    179712                    // 21760 B ; end 201472
// post-mainloop overlay (written only after the final mainloop barrier)
#define EP_H1   0                 // h1 [256 h][136 i] f32 = 139264
#define EP_W2   139264            // W2t [256 h][16 g]     = 16384 -> 155648
#define EP_H2   155648            // H2 [16 g][132 i]      = 8448  -> 164096
// small consts staged at kernel start (ABOVE everything: >= 201472)
#define EP_B1   201472            // 256 f -> 202496
#define EP_B2   202496            // 16 f  -> 202560
#define EP_W3   202560            // 16 f  -> 202624
#define EP_B3   202624            // 1 f
#define SMEM_BYTES 202752

// ---------------- device scratch ----------------
__device__ __align__(16) __half g_W1h[H1_ * D_]; // W1 in fp16
__device__ __align__(16) float g_W2t[H1_ * H2_]; // W2 transposed [h][g]
__device__ __align__(16) float g_WpT[IV * PH_];  // Wp transposed [k][ph]
__device__ float g_fc[B_ * IV];

// ---------------- PTX helpers ----------------
__device__ __forceinline__ uint32_t smem_u32(const void* p) {
    uint32_t a;
    asm("{ .reg .u64 t; cvta.to.shared.u64 t, %1; cvt.u32.u64 %0, t; }"
        : "=r"(a) : "l"(p));
    return a;
}
#define PACK2(out, lo, hi) \
    asm("mov.b64 %0, {%1, %2};" : "=l"(out) : "r"(lo), "r"(hi))
#define UNPACK2(lo, hi, in) \
    asm("mov.b64 {%0, %1}, %2;" : "=r"(lo), "=r"(hi) : "l"(in))
#define FMA2(d, a, b, c) \
    asm("fma.rn.f32x2 %0, %1, %2, %3;" : "=l"(d) : "l"(a), "l"(b), "l"(c))

// pack two f32 -> f16x2: first arg -> LOWER half, second -> UPPER half
__device__ __forceinline__ uint32_t cvt_f16x2(float lo, float hi) {
    uint32_t d;
    asm("cvt.rn.f16x2.f32 %0, %1, %2;" : "=r"(d) : "f"(hi), "f"(lo));
    return d;
}

// cp.async 16B with zero-fill src-size (sm_80+ standard PTX)
#define CP_ASYNC16(dst_u32, src_ptr, vb) \
    asm volatile("cp.async.cg.shared.global [%0], [%1], 16, %2;" \
                 :: "r"(dst_u32), "l"(src_ptr), "r"(vb) : "memory")
#define CP_COMMIT() asm volatile("cp.async.commit_group;" ::: "memory")
#define CP_WAIT0()  asm volatile("cp.async.wait_group 0;" ::: "memory")

// ldmatrix x4 (sm_75+ standard PTX) — native b16 on fp16 A
#define LDSM_X4(r0, r1, r2, r3, addr) \
    asm volatile("ldmatrix.sync.aligned.m8n8.x4.shared.b16 {%0,%1,%2,%3}, [%4];" \
                 : "=r"(r0), "=r"(r1), "=r"(r2), "=r"(r3) : "r"(addr))

// fp16 warp MMA m16n8k16 (sm_80+ standard PTX)
__device__ __forceinline__ void mma_f16(float c[4],
                                        uint32_t a0, uint32_t a1,
                                        uint32_t a2, uint32_t a3,
                                        uint32_t b0, uint32_t b1) {
    asm volatile(
        "mma.sync.aligned.m16n8k16.row.col.f32.f16.f16.f32 "
        "{%0,%1,%2,%3}, {%4,%5,%6,%7}, {%8,%9}, {%0,%1,%2,%3};"
        : "+f"(c[0]), "+f"(c[1]), "+f"(c[2]), "+f"(c[3])
        : "r"(a0), "r"(a1), "r"(a2), "r"(a3), "r"(b0), "r"(b1));
}

// ---------------------------------------------------------------------------
// merged prep kernel: W1->fp16, W2 transpose, Wp transpose
// ---------------------------------------------------------------------------
__global__ void prep_all(const float* __restrict__ W1,
                         const float* __restrict__ W2,
                         const float* __restrict__ Wp)
{
    const int i = blockIdx.x * 256 + threadIdx.x;
    if (i < H1_ * D_) g_W1h[i] = __float2half_rn(W1[i]);
    if (i < H2_ * H1_) {
        const int g = i / H1_, h = i % H1_;
        g_W2t[h * H2_ + g] = W2[i];
    }
    if (i < PH_ * IV) {
        const int ph = i / IV, k = i % IV;
        g_WpT[k * PH_ + ph] = Wp[i];
    }
}

// ---------------------------------------------------------------------------
// Kernel 1: fused section MLP. Grid (NIT, B_), 512 threads (16 warps).
// GEMM: D[h(256,M), i(128,N)] = W1[h,k] * state[k,i], K=800, fp16 inputs.
// Warp grid 4(M) x 4(N); warp tile 64h x 32i; 64 acc f32/thread.
// Per stage: cp.async lands f32 B -> block-wide pack to f16x2 pairs (Bh) ->
// hot loop does ONE LDS.32 per B fragment register (no CVT in loop).
// ---------------------------------------------------------------------------
__global__ __launch_bounds__(512, 1)
void section_kernel(const float* __restrict__ state,
                    const float* __restrict__ b1,
                    const float* __restrict__ b2,
                    const float* __restrict__ W3,
                    const float* __restrict__ b3)
{
    extern __shared__ char smc[];
    const uint32_t smem_base = smem_u32(smc);
    const int tid  = threadIdx.x;
    const int wid  = tid >> 5;
    const int lane = tid & 31;
    const int g4   = lane >> 2;
    const int tig  = lane & 3;
    const int b    = blockIdx.y;
    const int i0   = blockIdx.x * IT_M;

    const int warp_h = (wid & 3) * 64;    // M offset of warp tile
    const int warp_i = (wid >> 2) * 32;   // N offset of warp tile

    // ---- stage small consts (above the ring; never clobbered) ----
    {
        if (tid < 256) ((float*)(smc + EP_B1))[tid] = b1[tid];
        if (tid < 16) {
            ((float*)(smc + EP_B2))[tid] = b2[tid];
            ((float*)(smc + EP_W3))[tid] = W3[tid];
        }
        if (tid == 0) *(float*)(smc + EP_B3) = b3[0];
    }

    // ---- cp.async staging mapping (512 threads) ----
    // A: 256 rows x 160B = 2560 x 16B ops -> 5/thread
    int arow[5], aqd[5];
    #pragma unroll
    for (int j = 0; j < 5; j++) {
        const int o = tid + 512 * j;
        arow[j] = o / 10;
        aqd[j]  = o % 10;
    }
    // B: 80 rows x 512B = 2560 x 16B ops -> 5/thread
    const int biq = tid & 31;             // i-quad
    const int bkb = tid >> 5;             // k base (0..15), rows bkb + 16j
    const int bgi = i0 + biq * 4;
    const unsigned bvb = (bgi < IV) ? 16u : 0u;   // IV%4==0 -> all-or-nothing
    const size_t bcol = bvb ? (size_t)bgi : 0;

    const float* Sb = state + (size_t)b * D_ * IV;

    auto issue_stage = [&](int k0, int slot) {
        const uint32_t As = smem_base + A_SL(slot);
        const uint32_t Bs = smem_base + BF_SL(slot);
        #pragma unroll
        for (int j = 0; j < 5; j++) {
            CP_ASYNC16(As + arow[j] * 176 + aqd[j] * 16,
                       (const char*)g_W1h + (size_t)arow[j] * (D_ * 2)
                                          + k0 * 2 + aqd[j] * 16, 16u);
        }
        #pragma unroll
        for (int j = 0; j < 5; j++) {
            const int k = bkb + 16 * j;
            CP_ASYNC16(Bs + k * 560 + biq * 16,
                       Sb + (size_t)(k0 + k) * IV + bcol, bvb);
        }
    };

    // ldmatrix per-lane base: row = warp_h + (lane&15), col half = (lane>>4)*16B
    const uint32_t alane_off =
        (uint32_t)((warp_h + (lane & 15)) * 176 + ((lane >> 4) * 16));
    const int bcol0 = warp_i + g4;

    // prologue: fill slot 0
    issue_stage(0, 0);       CP_COMMIT();

    float c[4][4][4];
    #pragma unroll
    for (int mf = 0; mf < 4; mf++)
        #pragma unroll
        for (int nf = 0; nf < 4; nf++)
            #pragma unroll
            for (int r = 0; r < 4; r++) c[mf][nf][r] = 0.f;

    #pragma unroll 1
    for (int s = 0; s < NST; s++) {
        const int slot = s & 1;
        CP_WAIT0();                      // stage s landed
        __syncthreads();                 // visible; stage s-1 compute + Bh reads done

        if (s + 1 < NST) issue_stage((s + 1) * KS, slot ^ 1);
        CP_COMMIT();                     // always commit (exact accounting)

        // ---- pack B f32 -> Bh f16x2 pairs: word(k2,i) = (f16 B[2k2][i], f16 B[2k2+1][i])
        {
            const float* Bf = (const float*)(smc + BF_SL(slot));
            uint32_t* Bh = (uint32_t*)(smc + BH_OFF);
            #pragma unroll
            for (int j = 0; j < 3; j++) {
                const int idx = tid + 512 * j;       // 40 rows x 32 i-quads = 1280
                if (j < 2 || idx < 1280) {
                    const int row = idx >> 5, ciq = idx & 31;
                    const float4 lo = *(const float4*)(Bf + (2 * row)     * 140 + ciq * 4);
                    const float4 hi = *(const float4*)(Bf + (2 * row + 1) * 140 + ciq * 4);
                    uint4 o;
                    o.x = cvt_f16x2(lo.x, hi.x);
                    o.y = cvt_f16x2(lo.y, hi.y);
                    o.z = cvt_f16x2(lo.z, hi.z);
                    o.w = cvt_f16x2(lo.w, hi.w);
                    *(uint4*)(Bh + row * 136 + ciq * 4) = o;
                }
            }
        }
        __syncthreads();                 // Bh ready for all warps

        const uint32_t Aad = smem_base + A_SL(slot) + alane_off;
        const uint32_t* BhB = (const uint32_t*)(smc + BH_OFF) + bcol0;

        #pragma unroll
        for (int k16 = 0; k16 < 5; k16++) {
            uint32_t a[4][4];
            #pragma unroll
            for (int mf = 0; mf < 4; mf++)
                LDSM_X4(a[mf][0], a[mf][1], a[mf][2], a[mf][3],
                        Aad + mf * 2816 + k16 * 32);
            // B frags: single LDS.32 per register (pre-packed pairs)
            // b0: k2 = k16*8 + tig ; b1: k2 = k16*8 + 4 + tig
            const uint32_t* bq = BhB + (k16 * 8 + tig) * 136;
            uint32_t bf[4][2];
            #pragma unroll
            for (int nf = 0; nf < 4; nf++) {
                bf[nf][0] = bq[nf * 8];
                bf[nf][1] = bq[4 * 136 + nf * 8];
            }
            #pragma unroll
            for (int mf = 0; mf < 4; mf++)
                #pragma unroll
                for (int nf = 0; nf < 4; nf++)
                    mma_f16(c[mf][nf], a[mf][0], a[mf][1], a[mf][2], a[mf][3],
                            bf[nf][0], bf[nf][1]);
        }
    }
    __syncthreads();   // all MMAs done before h1 overlay overwrites the ring

    // ---- epilogue: relu(D + b1) -> h1[h][i] (stride 136), float2 stores ----
    {
        const float* eB1 = (const float*)(smc + EP_B1);
        float* h1 = (float*)(smc + EP_H1);
        #pragma unroll
        for (int mf = 0; mf < 4; mf++) {
            #pragma unroll
            for (int half = 0; half < 2; half++) {
                const int h = warp_h + mf * 16 + g4 + half * 8;
                const float bv = eB1[h];
                #pragma unroll
                for (int nf = 0; nf < 4; nf++) {
                    const int i = warp_i + nf * 8 + 2 * tig;
                    float2 v;
                    v.x = fmaxf(c[mf][nf][half * 2]     + bv, 0.f);
                    v.y = fmaxf(c[mf][nf][half * 2 + 1] + bv, 0.f);
                    *(float2*)(h1 + h * 136 + i) = v;
                }
            }
        }
        // stage W2t into its post-ring home (disjoint from h1)
        float* eW2 = (float*)(smc + EP_W2);
        for (int idx = tid; idx < H1_ * H2_; idx += 512) eW2[idx] = g_W2t[idx];
    }
    __syncthreads();

    // ---- layer 2: H2[g][i] = relu(W2 @ h1 + b2); 4 gq x 128 i, f32x2 ----
    {
        const int gq = tid >> 7;          // 0..3 -> 4 g each (2 pairs)
        const int il = tid & 127;
        const float* h1 = (const float*)(smc + EP_H1);
        const float* eW2 = (const float*)(smc + EP_W2);
        const float* eB2 = (const float*)(smc + EP_B2);

        unsigned long long a2p[2];
        #pragma unroll
        for (int p = 0; p < 2; p++)
            a2p[p] = *(const unsigned long long*)(eB2 + gq * 4 + p * 2);

        #pragma unroll 8
        for (int h = 0; h < H1_; h++) {
            const uint32_t xu = __float_as_uint(h1[h * 136 + il]);
            unsigned long long xx; PACK2(xx, xu, xu);
            const unsigned long long* wp =
                (const unsigned long long*)(eW2 + h * H2_ + gq * 4);
            FMA2(a2p[0], xx, wp[0], a2p[0]);
            FMA2(a2p[1], xx, wp[1], a2p[1]);
        }
        float* H2s = (float*)(smc + EP_H2);          // [16][132]
        #pragma unroll
        for (int p = 0; p < 2; p++) {
            uint32_t lo, hi;
            UNPACK2(lo, hi, a2p[p]);
            H2s[(gq * 4 + p * 2)     * 132 + il] = fmaxf(__uint_as_float(lo), 0.f);
            H2s[(gq * 4 + p * 2 + 1) * 132 + il] = fmaxf(__uint_as_float(hi), 0.f);
        }
    }
    __syncthreads();

    // ---- layer 3: sec[i] = W3 @ H2 + b3 -> g_fc ----
    if (tid < IT_M) {
        const float* H2s = (const float*)(smc + EP_H2);
        const float* eW3 = (const float*)(smc + EP_W3);
        float sec = *(const float*)(smc + EP_B3);
        #pragma unroll
        for (int g = 0; g < H2_; g++)
            sec += eW3[g] * H2s[g * 132 + tid];
        const int gi = i0 + tid;
        if (gi < IV) g_fc[b * IV + gi] = sec;
    }
}

// ---------------------------------------------------------------------------
// Kernel 2: predictor. Grid 64 blocks x 256 thr; 4 batches per block.
// ---------------------------------------------------------------------------
__global__ __launch_bounds__(256)
void pred_kernel(const float* __restrict__ bp,
                 const float* __restrict__ Wv, const float* __restrict__ bv,
                 float* __restrict__ out)
{
    __shared__ float fcsT[IV * 4 + 8];     // [k][4 batches]
    __shared__ float red[4][PH_];
    const int b0 = blockIdx.x * 4;
    const int tid = threadIdx.x;

    #pragma unroll
    for (int r = 0; r < 4; r++)
        for (int k = tid; k < IV; k += 256)
            fcsT[k * 4 + r] = g_fc[(b0 + r) * IV + k];
    __syncthreads();

    const int ph = tid;
    unsigned long long a01 = 0ull, a23 = 0ull;
    const float* wpt = g_WpT + ph;
    #pragma unroll 4
    for (int k = 0; k < IV; k++) {
        const uint32_t wu = __float_as_uint(wpt[(size_t)k * PH_]);   // coalesced
        unsigned long long ww; PACK2(ww, wu, wu);
        const unsigned long long p01 = *(const unsigned long long*)(fcsT + k * 4);
        const unsigned long long p23 = *(const unsigned long long*)(fcsT + k * 4 + 2);
        FMA2(a01, ww, p01, a01);
        FMA2(a23, ww, p23, a23);
    }
    uint32_t u0, u1, u2, u3;
    UNPACK2(u0, u1, a01);
    UNPACK2(u2, u3, a23);
    const float bpv = bp[ph], wvv = Wv[ph];
    red[0][ph] = fmaxf(__uint_as_float(u0) + bpv, 0.f) * wvv;
    red[1][ph] = fmaxf(__uint_as_float(u1) + bpv, 0.f) * wvv;
    red[2][ph] = fmaxf(__uint_as_float(u2) + bpv, 0.f) * wvv;
    red[3][ph] = fmaxf(__uint_as_float(u3) + bpv, 0.f) * wvv;
    __syncthreads();
    for (int s = 128; s > 0; s >>= 1) {
        if (tid < s) {
            #pragma unroll
            for (int r = 0; r < 4; r++) red[r][tid] += red[r][tid + s];
        }
        __syncthreads();
    }
    if (tid == 0) {
        const float bvv = bv[0];
        #pragma unroll
        for (int r = 0; r < 4; r++) out[b0 + r] = red[r][0] + bvv;
    }
}

// ---------------------------------------------------------------------------
extern "C" void kernel_launch(void* const* d_in, const int* in_sizes, int n_in,
                              void* d_out, int out_size)
{
    const float* state = (const float*)d_in[0];
    const float* W1    = (const float*)d_in[1];
    const float* b1    = (const float*)d_in[2];
    const float* W2    = (const float*)d_in[3];
    const float* b2    = (const float*)d_in[4];
    const float* W3    = (const float*)d_in[5];
    const float* b3    = (const float*)d_in[6];
    const float* Wp    = (const float*)d_in[7];
    const float* bp    = (const float*)d_in[8];
    const float* Wv    = (const float*)d_in[9];
    const float* bv    = (const float*)d_in[10];
    float* out = (float*)d_out;

    cudaFuncSetAttribute(section_kernel,
                         cudaFuncAttributeMaxDynamicSharedMemorySize, SMEM_BYTES);

    prep_all<<<(PH_ * IV + 255) / 256, 256>>>(W1, W2, Wp);

    dim3 grid(NIT, B_);
    section_kernel<<<grid, 512, SMEM_BYTES>>>(state, b1, b2, W3, b3);
    pred_kernel<<<64, 256>>>(bp, Wv, bv, out);
}